// round 2
// baseline (speedup 1.0000x reference)
#include <cuda_runtime.h>
#include <cstddef>

// Problem constants (B=4096, n=512, m=1024 per reference setup_inputs)
#define Bsz 4096
#define Nn  512
#define Mm  1024
#define STEPC 0.01f
#define TOLV 1e-5f

// ---------------- device scratch (allocation-free) ----------------
__device__ __align__(128) float g_Q[Mm * Mm];        // 4 MB
__device__ __align__(128) float g_xu[Bsz * Nn];      // 8 MB
__device__ __align__(128) float g_c[(size_t)Bsz * Mm];       // 16 MB
__device__ __align__(128) float g_lam0[(size_t)Bsz * Mm];    // 16 MB
__device__ __align__(128) float g_lam1[(size_t)Bsz * Mm];    // 16 MB
__device__ __align__(128) float g_z[Bsz * Nn];       // 8 MB
__device__ __align__(128) float g_act[(size_t)Bsz * Mm];     // 16 MB
__device__ __align__(128) float g_msk[(size_t)Bsz * Mm];     // 16 MB

enum { EPI_NONE = 0, EPI_SUB_B, EPI_LAM, EPI_LAM_MASK, EPI_RES, EPI_ACTIVE, EPI_MASKED };

// ---------------------------------------------------------------------------
// Generic fused SGEMM: C = epilogue( A @ B  or  A @ B^T )
//  A: [M,K] row-major.  B: !TB -> [K,N] row-major ; TB -> [N,K] row-major.
//  All of M,N multiples of 128; K multiple of 16 (true for all call sites).
// Epilogues:
//  EPI_NONE    : C = acc
//  EPI_SUB_B   : C = acc - e1[col]                      (e1 = b vector)
//  EPI_LAM     : C = relu(A[r,col] - step*(acc - e1[r,col]))        (N==K)
//  EPI_LAM_MASK: C = relu(A[r,col] - step*(acc - e1[r,col]))*e2[r,col]
//  EPI_RES     : C = e1[r,col] - acc
//  EPI_ACTIVE  : C = (acc >= e1[col] - TOL) ? 1 : 0     (e1 = b vector)
//  EPI_MASKED  : C = acc * e1[r,col]
// ---------------------------------------------------------------------------
template <bool TB, int EPI>
__global__ void __launch_bounds__(256, 2) sgemm(
    const float* __restrict__ Ag, const float* __restrict__ Bg,
    float* __restrict__ Cg, int M, int N, int K,
    const float* __restrict__ e1, const float* __restrict__ e2)
{
    constexpr int BM = 128, BN = 128, BK = 16;
    __shared__ float As[BK][BM];
    __shared__ float Bs[BK][BN];

    const int tid  = threadIdx.x;
    const int bm0  = blockIdx.y * BM;
    const int bn0  = blockIdx.x * BN;
    const int cRow = (tid >> 4) * 8;   // 0..120
    const int cCol = (tid & 15) * 8;   // 0..120

    float acc[8][8];
#pragma unroll
    for (int i = 0; i < 8; i++)
#pragma unroll
        for (int j = 0; j < 8; j++) acc[i][j] = 0.f;

    for (int k0 = 0; k0 < K; k0 += BK) {
        // ---- load A tile (BM x BK), store transposed As[k][m] ----
#pragma unroll
        for (int l = 0; l < 2; l++) {
            int f   = tid + l * 256;        // float4 index 0..511
            int row = f >> 2;               // 0..127
            int c4  = f & 3;                // 0..3
            float4 v = *(const float4*)&Ag[(size_t)(bm0 + row) * K + k0 + c4 * 4];
            As[c4 * 4 + 0][row] = v.x;
            As[c4 * 4 + 1][row] = v.y;
            As[c4 * 4 + 2][row] = v.z;
            As[c4 * 4 + 3][row] = v.w;
        }
        // ---- load B tile ----
        if (TB) {
#pragma unroll
            for (int l = 0; l < 2; l++) {
                int f   = tid + l * 256;
                int row = f >> 2;           // n within tile
                int c4  = f & 3;
                float4 v = *(const float4*)&Bg[(size_t)(bn0 + row) * K + k0 + c4 * 4];
                Bs[c4 * 4 + 0][row] = v.x;
                Bs[c4 * 4 + 1][row] = v.y;
                Bs[c4 * 4 + 2][row] = v.z;
                Bs[c4 * 4 + 3][row] = v.w;
            }
        } else {
#pragma unroll
            for (int l = 0; l < 2; l++) {
                int f   = tid + l * 256;
                int row = f >> 5;           // k within tile (0..15)
                int c4  = f & 31;           // float4 within row
                float4 v = *(const float4*)&Bg[(size_t)(k0 + row) * N + bn0 + c4 * 4];
                *(float4*)&Bs[row][c4 * 4] = v;
            }
        }
        __syncthreads();

#pragma unroll
        for (int k = 0; k < BK; k++) {
            float4 a0 = *(const float4*)&As[k][cRow];
            float4 a1 = *(const float4*)&As[k][cRow + 4];
            float4 b0 = *(const float4*)&Bs[k][cCol];
            float4 b1 = *(const float4*)&Bs[k][cCol + 4];
            float a[8] = {a0.x, a0.y, a0.z, a0.w, a1.x, a1.y, a1.z, a1.w};
            float b[8] = {b0.x, b0.y, b0.z, b0.w, b1.x, b1.y, b1.z, b1.w};
#pragma unroll
            for (int i = 0; i < 8; i++)
#pragma unroll
                for (int j = 0; j < 8; j++) acc[i][j] += a[i] * b[j];
        }
        __syncthreads();
    }

    // ---- epilogue ----
#pragma unroll
    for (int i = 0; i < 8; i++) {
        const int r = bm0 + cRow + i;
#pragma unroll
        for (int j = 0; j < 8; j++) {
            const int cl   = bn0 + cCol + j;
            const size_t idx = (size_t)r * N + cl;
            const float v  = acc[i][j];
            if (EPI == EPI_NONE) {
                Cg[idx] = v;
            } else if (EPI == EPI_SUB_B) {
                Cg[idx] = v - e1[cl];
            } else if (EPI == EPI_LAM) {
                float lam = Ag[(size_t)r * K + cl];
                Cg[idx] = fmaxf(lam - STEPC * (v - e1[idx]), 0.f);
            } else if (EPI == EPI_LAM_MASK) {
                float lam = Ag[(size_t)r * K + cl];
                Cg[idx] = fmaxf(lam - STEPC * (v - e1[idx]), 0.f) * e2[idx];
            } else if (EPI == EPI_RES) {
                Cg[idx] = e1[idx] - v;
            } else if (EPI == EPI_ACTIVE) {
                Cg[idx] = (v >= e1[cl] - TOLV) ? 1.f : 0.f;
            } else if (EPI == EPI_MASKED) {
                Cg[idx] = v * e1[idx];
            }
        }
    }
}

// ---------------- small elementwise kernels ----------------
__global__ void add_kernel(const float* __restrict__ x, const float* __restrict__ u,
                           float* __restrict__ o, int n)
{
    int i = blockIdx.x * blockDim.x + threadIdx.x;
    if (i < n) o[i] = x[i] + u[i];
}

// first PGD iteration from lam=0:  lam1 = relu(step * c)
__global__ void lam_init(const float* __restrict__ c, float* __restrict__ lam, int n)
{
    int i = blockIdx.x * blockDim.x + threadIdx.x;
    if (i < n) lam[i] = fmaxf(STEPC * c[i], 0.f);
}

// first masked PGD iteration: lam1 = relu(step * masked) * active
__global__ void lam_init_mask(const float* __restrict__ m, const float* __restrict__ a,
                              float* __restrict__ lam, int n)
{
    int i = blockIdx.x * blockDim.x + threadIdx.x;
    if (i < n) lam[i] = fmaxf(STEPC * m[i], 0.f) * a[i];
}

// ---------------------------------------------------------------------------
extern "C" void kernel_launch(void* const* d_in, const int* in_sizes, int n_in,
                              void* d_out, int out_size)
{
    const float* x = (const float*)d_in[0];
    const float* u = (const float*)d_in[1];
    const float* A = (const float*)d_in[2];   // [m, n] row-major
    const float* b = (const float*)d_in[3];   // [m]
    float* out = (float*)d_out;               // [B, n]

    float *Q, *xu, *c, *lam0, *lam1, *z, *act, *msk;
    cudaGetSymbolAddress((void**)&Q,    g_Q);
    cudaGetSymbolAddress((void**)&xu,   g_xu);
    cudaGetSymbolAddress((void**)&c,    g_c);
    cudaGetSymbolAddress((void**)&lam0, g_lam0);
    cudaGetSymbolAddress((void**)&lam1, g_lam1);
    cudaGetSymbolAddress((void**)&z,    g_z);
    cudaGetSymbolAddress((void**)&act,  g_act);
    cudaGetSymbolAddress((void**)&msk,  g_msk);

    const dim3 blk(256);
    const dim3 gQ(Mm / 128, Mm / 128);       // 8x8
    const dim3 gBm(Mm / 128, Bsz / 128);     // 8x32
    const dim3 gBn(Nn / 128, Bsz / 128);     // 4x32
    const int  EW = 256;

    // 1) Q = A @ A^T                    [1024,1024,K=512]
    sgemm<true, EPI_NONE><<<gQ, blk>>>(A, A, Q, Mm, Mm, Nn, nullptr, nullptr);

    // 2) xu = x + u
    add_kernel<<<(Bsz * Nn) / EW, EW>>>(x, u, xu, Bsz * Nn);

    // 3) c = xu @ A^T - b               [4096,1024,K=512]
    sgemm<true, EPI_SUB_B><<<gBm, blk>>>(xu, A, c, Bsz, Mm, Nn, b, nullptr);

    // 4) PGD iter 1 (lam=0): lam = relu(step*c)
    lam_init<<<((size_t)Bsz * Mm) / EW, EW>>>(c, lam0, Bsz * Mm);

    // 5) PGD iters 2..50: lam <- relu(lam - step*(lam@Q - c))
    float* cur = lam0;
    float* nxt = lam1;
    for (int it = 1; it < 50; it++) {
        sgemm<false, EPI_LAM><<<gBm, blk>>>(cur, Q, nxt, Bsz, Mm, Mm, c, nullptr);
        float* t = cur; cur = nxt; nxt = t;
    }

    // 6) z = xu - lam @ A               [4096,512,K=1024]
    sgemm<false, EPI_RES><<<gBn, blk>>>(cur, A, z, Bsz, Nn, Mm, xu, nullptr);

    // 7) active = (z @ A^T >= b - TOL)
    sgemm<true, EPI_ACTIVE><<<gBm, blk>>>(z, A, act, Bsz, Mm, Nn, b, nullptr);

    // 8) masked = (u @ A^T) * active
    sgemm<true, EPI_MASKED><<<gBm, blk>>>(u, A, msk, Bsz, Mm, Nn, act, nullptr);

    // 9) masked PGD iter 1: lam = relu(step*masked)*active
    lam_init_mask<<<((size_t)Bsz * Mm) / EW, EW>>>(msk, act, lam0, Bsz * Mm);

    // 10) masked PGD iters 2..10
    cur = lam0; nxt = lam1;
    for (int it = 1; it < 10; it++) {
        sgemm<false, EPI_LAM_MASK><<<gBm, blk>>>(cur, Q, nxt, Bsz, Mm, Mm, msk, act);
        float* t = cur; cur = nxt; nxt = t;
    }

    // 11) out = u - lam @ A             [4096,512,K=1024]
    sgemm<false, EPI_RES><<<gBn, blk>>>(cur, A, out, Bsz, Nn, Mm, u, nullptr);
}

// round 4
// speedup vs baseline: 3.3051x; 3.3051x over previous
#include <cuda_runtime.h>
#include <cuda_bf16.h>
#include <cstddef>
#include <cstdint>

// Problem constants (B=4096, n=512, m=1024)
#define Bsz 4096
#define Nn  512
#define Mm  1024
#define STEPC 0.01f
#define TOLV 1e-5f

// ---- tensor-core PGD tile config ----
#define TM 128
#define TN 256
#define KC 64
#define NCH (Mm / KC)          // 16 K-chunks
#define OFF_ALO 16384
#define OFF_BHI 32768
#define OFF_BLO 65536
#define STG_SZ  98304          // 96 KB per stage
#define DSMEM   (2 * STG_SZ + 1024)

// tcgen05 is arch-specific: only present in the sm_103a device pass.
#if defined(__CUDA_ARCH__) && defined(__CUDA_ARCH_FEAT_SM103_ALL)
#define HAS_TCGEN05 1
#else
#define HAS_TCGEN05 0
#endif

// ---------------- device scratch (allocation-free) ----------------
__device__ __align__(128) float g_Q[Mm * Mm];
__device__ __align__(128) float g_xu[Bsz * Nn];
__device__ __align__(128) float g_c[(size_t)Bsz * Mm];
__device__ __align__(128) float g_msk[(size_t)Bsz * Mm];
__device__ __align__(128) float g_act[(size_t)Bsz * Mm];
__device__ __align__(128) float g_z[Bsz * Nn];
__device__ __align__(128) float g_lamf[(size_t)Bsz * Mm];
__device__ __align__(128) __nv_bfloat16 g_Qhi[Mm * Mm];
__device__ __align__(128) __nv_bfloat16 g_Qlo[Mm * Mm];
__device__ __align__(128) __nv_bfloat16 g_lAhi[(size_t)Bsz * Mm];
__device__ __align__(128) __nv_bfloat16 g_lAlo[(size_t)Bsz * Mm];
__device__ __align__(128) __nv_bfloat16 g_lBhi[(size_t)Bsz * Mm];
__device__ __align__(128) __nv_bfloat16 g_lBlo[(size_t)Bsz * Mm];

// ---------------- PTX helpers (generic; safe on all targets) ----------------
__device__ __forceinline__ uint32_t s2u(const void* p) {
    uint32_t a;
    asm("{ .reg .u64 t; cvta.to.shared.u64 t, %1; cvt.u32.u64 %0, t; }"
        : "=r"(a) : "l"(p));
    return a;
}

__device__ __forceinline__ void cpa16(uint32_t dst, const void* src) {
    asm volatile("cp.async.cg.shared.global [%0], [%1], 16;"
                 :: "r"(dst), "l"(src));
}

__device__ __forceinline__ void mbar_init(uint32_t a, uint32_t cnt) {
    asm volatile("mbarrier.init.shared.b64 [%0], %1;" :: "r"(a), "r"(cnt) : "memory");
}

__device__ __forceinline__ void mbar_wait(uint32_t a, uint32_t phase) {
    uint32_t done = 0;
    while (!done) {
        asm volatile(
            "{ .reg .pred p; mbarrier.try_wait.parity.shared.b64 p, [%1], %2; "
            "selp.b32 %0, 1, 0, p; }"
            : "=r"(done) : "r"(a), "r"(phase) : "memory");
    }
}

// SW128 K-major SMEM descriptor (LBO=1, SBO=64, version=1, layout=SW128)
__device__ __forceinline__ uint64_t mkdesc(uint32_t addr) {
    return ((uint64_t)2 << 61) | ((uint64_t)1 << 46) | ((uint64_t)64 << 32)
         | ((uint64_t)1 << 16) | ((addr >> 4) & 0x3FFF);
}

// idesc kind::f16: dtype=F32, atype=btype=BF16, N=TN, M=128
#define PGD_IDESC ((1u<<4) | (1u<<7) | (1u<<10) | ((TN/8)<<17) | ((128/16)<<24))

__device__ __forceinline__ float bfbits2f(uint16_t u) {
    __nv_bfloat16_raw r; r.x = u;
    return __bfloat162float(__nv_bfloat16(r));
}
__device__ __forceinline__ uint16_t f2bfbits(float f) {
    __nv_bfloat16 h = __float2bfloat16(f);
    __nv_bfloat16_raw r = (__nv_bfloat16_raw)h;
    return r.x;
}

#if HAS_TCGEN05
// ---------------- tcgen05 helpers (sm_103a pass only) ----------------
__device__ __forceinline__ void mma_f16_ss(uint32_t d, uint64_t a, uint64_t b,
                                           uint32_t idesc, uint32_t en) {
    asm volatile(
        "{\n\t.reg .pred p;\n\tsetp.ne.u32 p, %5, 0;\n\t"
        "tcgen05.mma.cta_group::1.kind::f16 [%0], %1, %2, %3, {%4,%4,%4,%4}, p;\n\t}"
        :: "r"(d), "l"(a), "l"(b), "r"(idesc), "r"(0u), "r"(en) : "memory");
}

__device__ __forceinline__ void tc_commit(uint32_t mbar) {
    asm volatile(
        "tcgen05.commit.cta_group::1.mbarrier::arrive::one.shared::cluster.b64 [%0];"
        :: "r"(mbar) : "memory");
}

#define TC_ALLOC(sres, n) \
    asm volatile("tcgen05.alloc.cta_group::1.sync.aligned.shared::cta.b32 [%0], %1;" \
                 :: "r"(sres), "r"((uint32_t)(n)) : "memory")
#define TC_RELINQ() \
    asm volatile("tcgen05.relinquish_alloc_permit.cta_group::1.sync.aligned;")
#define TC_DEALLOC(t, n) \
    asm volatile("tcgen05.dealloc.cta_group::1.sync.aligned.b32 %0, %1;" :: "r"(t), "r"((uint32_t)(n)))
#define TC_FENCE_AFTER()  asm volatile("tcgen05.fence::after_thread_sync;" ::: "memory")
#define TC_WAIT_LD()      asm volatile("tcgen05.wait::ld.sync.aligned;" ::: "memory")

#define LDTM_X32(r, a) \
    asm volatile( \
        "tcgen05.ld.sync.aligned.32x32b.x32.b32 " \
        "{%0,%1,%2,%3,%4,%5,%6,%7,%8,%9,%10,%11,%12,%13,%14,%15," \
        "%16,%17,%18,%19,%20,%21,%22,%23,%24,%25,%26,%27,%28,%29,%30,%31}, [%32];" \
        : "=r"((r)[0]),"=r"((r)[1]),"=r"((r)[2]),"=r"((r)[3]), \
          "=r"((r)[4]),"=r"((r)[5]),"=r"((r)[6]),"=r"((r)[7]), \
          "=r"((r)[8]),"=r"((r)[9]),"=r"((r)[10]),"=r"((r)[11]), \
          "=r"((r)[12]),"=r"((r)[13]),"=r"((r)[14]),"=r"((r)[15]), \
          "=r"((r)[16]),"=r"((r)[17]),"=r"((r)[18]),"=r"((r)[19]), \
          "=r"((r)[20]),"=r"((r)[21]),"=r"((r)[22]),"=r"((r)[23]), \
          "=r"((r)[24]),"=r"((r)[25]),"=r"((r)[26]),"=r"((r)[27]), \
          "=r"((r)[28]),"=r"((r)[29]),"=r"((r)[30]),"=r"((r)[31]) \
        : "r"(a))
#endif  // HAS_TCGEN05

// ---------------------------------------------------------------------------
// Tensor-core PGD iteration:
//   acc = (Ahi+Alo) @ (Bhi+Blo)^T  (3 products, Q symmetric so B^T==Q)
//   v   = relu(lam_old - step*(acc - c))  [* act if masked]
//   write v as bf16 hi/lo (+ optional fp32)
// ---------------------------------------------------------------------------
__global__ void __launch_bounds__(256, 1) pgd_mma(
    const __nv_bfloat16* __restrict__ Ahi, const __nv_bfloat16* __restrict__ Alo,
    const __nv_bfloat16* __restrict__ Bhi, const __nv_bfloat16* __restrict__ Blo,
    const float* __restrict__ cc, const float* __restrict__ act,
    __nv_bfloat16* __restrict__ Ohi, __nv_bfloat16* __restrict__ Olo,
    float* __restrict__ Of32, int writeF32, int masked)
{
#if HAS_TCGEN05
    extern __shared__ char draw[];
    const uint32_t dsm = (s2u(draw) + 1023u) & ~1023u;

    __shared__ uint32_t s_tmem;
    __shared__ __align__(8) uint64_t s_bar[3];   // empty0, empty1, done

    const int tid  = threadIdx.x;
    const int wid  = tid >> 5;
    const int lane = tid & 31;
    const int bm0  = blockIdx.y * TM;
    const int bn0  = blockIdx.x * TN;

    const uint32_t e0 = s2u(&s_bar[0]);
    const uint32_t e1 = s2u(&s_bar[1]);
    const uint32_t db = s2u(&s_bar[2]);

    if (wid == 0) TC_ALLOC(s2u(&s_tmem), 256);
    if (tid == 0) { mbar_init(e0, 1); mbar_init(e1, 1); mbar_init(db, 1); }
    __syncthreads();
    uint32_t tmem;
    asm volatile("ld.shared.b32 %0, [%1];" : "=r"(tmem) : "r"(s2u(&s_tmem)));

    // -------- prefetch helper (all 256 threads) --------
    auto prefetch = [&](int ch) {
        const uint32_t st = dsm + (uint32_t)(ch & 1) * STG_SZ;
        const int k0 = ch * KC;
#pragma unroll
        for (int j = 0; j < 4; j++) {                      // A tiles: 128x64 bf16
            int cidx = tid + j * 256;
            int row = cidx >> 3, c16 = cidx & 7;
            uint32_t off = (uint32_t)(row * 128 + c16 * 16);
            uint32_t sw  = off ^ ((off >> 3) & 0x70);
            size_t g = (size_t)(bm0 + row) * Mm + k0 + c16 * 8;
            cpa16(st + sw,           Ahi + g);
            cpa16(st + OFF_ALO + sw, Alo + g);
        }
#pragma unroll
        for (int j = 0; j < 8; j++) {                      // B tiles: 256x64 bf16
            int cidx = tid + j * 256;
            int row = cidx >> 3, c16 = cidx & 7;
            uint32_t off = (uint32_t)(row * 128 + c16 * 16);
            uint32_t sw  = off ^ ((off >> 3) & 0x70);
            size_t g = (size_t)(bn0 + row) * Mm + k0 + c16 * 8;
            cpa16(st + OFF_BHI + sw, Bhi + g);
            cpa16(st + OFF_BLO + sw, Blo + g);
        }
        asm volatile("cp.async.commit_group;" ::: "memory");
    };

    uint32_t ph[2] = {0, 0};
    prefetch(0);

#pragma unroll 1
    for (int i = 0; i < NCH; i++) {
        if (i + 1 < NCH) {
            const int nb = (i + 1) & 1;
            if (i >= 1) { mbar_wait(nb ? e1 : e0, ph[nb]); ph[nb] ^= 1; }
            prefetch(i + 1);
        }
        if (i + 1 < NCH) asm volatile("cp.async.wait_group 1;" ::: "memory");
        else             asm volatile("cp.async.wait_group 0;" ::: "memory");
        __syncthreads();

        if (tid == 0) {
            asm volatile("fence.proxy.async.shared::cta;" ::: "memory");
            const uint32_t st = dsm + (uint32_t)(i & 1) * STG_SZ;
            const uint64_t dah = mkdesc(st);
            const uint64_t dal = mkdesc(st + OFF_ALO);
            const uint64_t dbh = mkdesc(st + OFF_BHI);
            const uint64_t dbl = mkdesc(st + OFF_BLO);
#pragma unroll
            for (int ks = 0; ks < 4; ks++) {
                mma_f16_ss(tmem, dah + ks * 2, dbh + ks * 2, PGD_IDESC,
                           (i == 0 && ks == 0) ? 0u : 1u);
                mma_f16_ss(tmem, dah + ks * 2, dbl + ks * 2, PGD_IDESC, 1u);
                mma_f16_ss(tmem, dal + ks * 2, dbh + ks * 2, PGD_IDESC, 1u);
            }
            tc_commit((i & 1) ? e1 : e0);
        }
    }

    if (tid == 0) tc_commit(db);
    mbar_wait(db, 0);
    TC_FENCE_AFTER();

    // -------- fused epilogue --------
    const int sp   = wid & 3;          // TMEM subpartition (row group)
    const int half = wid >> 2;         // column half (0 or 1) of the 256 cols
    const int r    = bm0 + sp * 32 + lane;

#pragma unroll 1
    for (int cb = 0; cb < 128; cb += 32) {
        uint32_t dreg[32];
        LDTM_X32(dreg, tmem + half * 128 + cb);
        TC_WAIT_LD();
        const size_t base = (size_t)r * Mm + bn0 + half * 128 + cb;
#pragma unroll
        for (int j0 = 0; j0 < 32; j0 += 4) {
            float4 cv = *(const float4*)&cc[base + j0];
            uint64_t h4 = *(const uint64_t*)&Ahi[base + j0];
            uint64_t l4 = *(const uint64_t*)&Alo[base + j0];
            float4 av;
            if (masked) av = *(const float4*)&act[base + j0];
            const float* cvp = (const float*)&cv;
            const float* avp = (const float*)&av;
            uint16_t oh[4], ol[4];
            float of[4];
#pragma unroll
            for (int k = 0; k < 4; k++) {
                float lamold = bfbits2f((uint16_t)(h4 >> (16 * k)))
                             + bfbits2f((uint16_t)(l4 >> (16 * k)));
                float acc = __uint_as_float(dreg[j0 + k]);
                float v = fmaxf(lamold - STEPC * (acc - cvp[k]), 0.f);
                if (masked) v *= avp[k];
                uint16_t hb = f2bfbits(v);
                oh[k] = hb;
                ol[k] = f2bfbits(v - bfbits2f(hb));
                of[k] = v;
            }
            uint64_t ohp = (uint64_t)oh[0] | ((uint64_t)oh[1] << 16)
                         | ((uint64_t)oh[2] << 32) | ((uint64_t)oh[3] << 48);
            uint64_t olp = (uint64_t)ol[0] | ((uint64_t)ol[1] << 16)
                         | ((uint64_t)ol[2] << 32) | ((uint64_t)ol[3] << 48);
            *(uint64_t*)&Ohi[base + j0] = ohp;
            *(uint64_t*)&Olo[base + j0] = olp;
            if (writeF32) *(float4*)&Of32[base + j0] = make_float4(of[0], of[1], of[2], of[3]);
        }
    }

    __syncthreads();
    if (wid == 0) { TC_RELINQ(); TC_DEALLOC(tmem, 256); }
#endif  // HAS_TCGEN05
}

// ---------------------------------------------------------------------------
// fp32 SIMT SGEMM (peripheral GEMMs)
// ---------------------------------------------------------------------------
enum { EPI_NONE = 0, EPI_SUB_B, EPI_RES, EPI_ACTIVE, EPI_MASKED };

template <bool TB, int EPI>
__global__ void __launch_bounds__(256, 2) sgemm(
    const float* __restrict__ Ag, const float* __restrict__ Bg,
    float* __restrict__ Cg, int M, int N, int K,
    const float* __restrict__ e1)
{
    constexpr int BM = 128, BN = 128, BK = 16;
    __shared__ float As[BK][BM];
    __shared__ float Bs[BK][BN];

    const int tid  = threadIdx.x;
    const int bm0  = blockIdx.y * BM;
    const int bn0  = blockIdx.x * BN;
    const int cRow = (tid >> 4) * 8;
    const int cCol = (tid & 15) * 8;

    float acc[8][8];
#pragma unroll
    for (int i = 0; i < 8; i++)
#pragma unroll
        for (int j = 0; j < 8; j++) acc[i][j] = 0.f;

    for (int k0 = 0; k0 < K; k0 += BK) {
#pragma unroll
        for (int l = 0; l < 2; l++) {
            int f = tid + l * 256, row = f >> 2, c4 = f & 3;
            float4 v = *(const float4*)&Ag[(size_t)(bm0 + row) * K + k0 + c4 * 4];
            As[c4 * 4 + 0][row] = v.x; As[c4 * 4 + 1][row] = v.y;
            As[c4 * 4 + 2][row] = v.z; As[c4 * 4 + 3][row] = v.w;
        }
        if (TB) {
#pragma unroll
            for (int l = 0; l < 2; l++) {
                int f = tid + l * 256, row = f >> 2, c4 = f & 3;
                float4 v = *(const float4*)&Bg[(size_t)(bn0 + row) * K + k0 + c4 * 4];
                Bs[c4 * 4 + 0][row] = v.x; Bs[c4 * 4 + 1][row] = v.y;
                Bs[c4 * 4 + 2][row] = v.z; Bs[c4 * 4 + 3][row] = v.w;
            }
        } else {
#pragma unroll
            for (int l = 0; l < 2; l++) {
                int f = tid + l * 256, row = f >> 5, c4 = f & 31;
                float4 v = *(const float4*)&Bg[(size_t)(k0 + row) * N + bn0 + c4 * 4];
                *(float4*)&Bs[row][c4 * 4] = v;
            }
        }
        __syncthreads();
#pragma unroll
        for (int k = 0; k < BK; k++) {
            float4 a0 = *(const float4*)&As[k][cRow];
            float4 a1 = *(const float4*)&As[k][cRow + 4];
            float4 b0 = *(const float4*)&Bs[k][cCol];
            float4 b1 = *(const float4*)&Bs[k][cCol + 4];
            float a[8] = {a0.x, a0.y, a0.z, a0.w, a1.x, a1.y, a1.z, a1.w};
            float b[8] = {b0.x, b0.y, b0.z, b0.w, b1.x, b1.y, b1.z, b1.w};
#pragma unroll
            for (int i = 0; i < 8; i++)
#pragma unroll
                for (int j = 0; j < 8; j++) acc[i][j] += a[i] * b[j];
        }
        __syncthreads();
    }

#pragma unroll
    for (int i = 0; i < 8; i++) {
        const int r = bm0 + cRow + i;
#pragma unroll
        for (int j = 0; j < 8; j++) {
            const int cl = bn0 + cCol + j;
            const size_t idx = (size_t)r * N + cl;
            const float v = acc[i][j];
            if (EPI == EPI_NONE)        Cg[idx] = v;
            else if (EPI == EPI_SUB_B)  Cg[idx] = v - e1[cl];
            else if (EPI == EPI_RES)    Cg[idx] = e1[idx] - v;
            else if (EPI == EPI_ACTIVE) Cg[idx] = (v >= e1[cl] - TOLV) ? 1.f : 0.f;
            else if (EPI == EPI_MASKED) Cg[idx] = v * e1[idx];
        }
    }
}

// ---------------- small elementwise kernels ----------------
__global__ void add_kernel(const float* __restrict__ x, const float* __restrict__ u,
                           float* __restrict__ o, int n)
{
    int i = blockIdx.x * blockDim.x + threadIdx.x;
    if (i < n) o[i] = x[i] + u[i];
}

__global__ void split_kernel(const float* __restrict__ s,
                             __nv_bfloat16* __restrict__ hi,
                             __nv_bfloat16* __restrict__ lo, int n)
{
    int i = blockIdx.x * blockDim.x + threadIdx.x;
    if (i < n) {
        float v = s[i];
        __nv_bfloat16 h = __float2bfloat16(v);
        hi[i] = h;
        lo[i] = __float2bfloat16(v - __bfloat162float(h));
    }
}

__global__ void lam_init_split(const float* __restrict__ c,
                               __nv_bfloat16* __restrict__ hi,
                               __nv_bfloat16* __restrict__ lo, int n)
{
    int i = blockIdx.x * blockDim.x + threadIdx.x;
    if (i < n) {
        float v = fmaxf(STEPC * c[i], 0.f);
        __nv_bfloat16 h = __float2bfloat16(v);
        hi[i] = h;
        lo[i] = __float2bfloat16(v - __bfloat162float(h));
    }
}

__global__ void lam_init_mask_split(const float* __restrict__ m, const float* __restrict__ a,
                                    __nv_bfloat16* __restrict__ hi,
                                    __nv_bfloat16* __restrict__ lo, int n)
{
    int i = blockIdx.x * blockDim.x + threadIdx.x;
    if (i < n) {
        float v = fmaxf(STEPC * m[i], 0.f) * a[i];
        __nv_bfloat16 h = __float2bfloat16(v);
        hi[i] = h;
        lo[i] = __float2bfloat16(v - __bfloat162float(h));
    }
}

// ---------------------------------------------------------------------------
extern "C" void kernel_launch(void* const* d_in, const int* in_sizes, int n_in,
                              void* d_out, int out_size)
{
    const float* x = (const float*)d_in[0];
    const float* u = (const float*)d_in[1];
    const float* A = (const float*)d_in[2];   // [m, n]
    const float* b = (const float*)d_in[3];   // [m]
    float* out = (float*)d_out;

    float *Q, *xu, *c, *msk, *act, *z, *lamf;
    __nv_bfloat16 *Qhi, *Qlo, *lAhi, *lAlo, *lBhi, *lBlo;
    cudaGetSymbolAddress((void**)&Q,    g_Q);
    cudaGetSymbolAddress((void**)&xu,   g_xu);
    cudaGetSymbolAddress((void**)&c,    g_c);
    cudaGetSymbolAddress((void**)&msk,  g_msk);
    cudaGetSymbolAddress((void**)&act,  g_act);
    cudaGetSymbolAddress((void**)&z,    g_z);
    cudaGetSymbolAddress((void**)&lamf, g_lamf);
    cudaGetSymbolAddress((void**)&Qhi,  g_Qhi);
    cudaGetSymbolAddress((void**)&Qlo,  g_Qlo);
    cudaGetSymbolAddress((void**)&lAhi, g_lAhi);
    cudaGetSymbolAddress((void**)&lAlo, g_lAlo);
    cudaGetSymbolAddress((void**)&lBhi, g_lBhi);
    cudaGetSymbolAddress((void**)&lBlo, g_lBlo);

    cudaFuncSetAttribute(pgd_mma, cudaFuncAttributeMaxDynamicSharedMemorySize, DSMEM);

    const dim3 blk(256);
    const dim3 gQ(Mm / 128, Mm / 128);
    const dim3 gBm(Mm / 128, Bsz / 128);
    const dim3 gBn(Nn / 128, Bsz / 128);
    const dim3 gT(Mm / TN, Bsz / TM);        // 4 x 32 = 128 CTAs
    const int EW = 256;

    // 1) Q = A @ A^T  (fp32)
    sgemm<true, EPI_NONE><<<gQ, blk>>>(A, A, Q, Mm, Mm, Nn, nullptr);
    // 2) split Q -> bf16 hi/lo
    split_kernel<<<(Mm * Mm) / EW, EW>>>(Q, Qhi, Qlo, Mm * Mm);
    // 3) xu = x + u
    add_kernel<<<(Bsz * Nn) / EW, EW>>>(x, u, xu, Bsz * Nn);
    // 4) c = xu @ A^T - b
    sgemm<true, EPI_SUB_B><<<gBm, blk>>>(xu, A, c, Bsz, Mm, Nn, b);
    // 5) PGD iter 1: lam = relu(step*c), split
    lam_init_split<<<(int)(((size_t)Bsz * Mm) / EW), EW>>>(c, lAhi, lAlo, Bsz * Mm);

    // 6) PGD iters 2..50 on tensor cores
    __nv_bfloat16 *curh = lAhi, *curl = lAlo, *nxth = lBhi, *nxtl = lBlo;
    for (int it = 1; it < 50; it++) {
        int last = (it == 49);
        pgd_mma<<<gT, blk, DSMEM>>>(curh, curl, Qhi, Qlo, c, nullptr,
                                    nxth, nxtl, lamf, last, 0);
        __nv_bfloat16* t;
        t = curh; curh = nxth; nxth = t;
        t = curl; curl = nxtl; nxtl = t;
    }

    // 7) z = xu - lam @ A
    sgemm<false, EPI_RES><<<gBn, blk>>>(lamf, A, z, Bsz, Nn, Mm, xu);
    // 8) active = (z @ A^T >= b - TOL)
    sgemm<true, EPI_ACTIVE><<<gBm, blk>>>(z, A, act, Bsz, Mm, Nn, b);
    // 9) masked = (u @ A^T) * active
    sgemm<true, EPI_MASKED><<<gBm, blk>>>(u, A, msk, Bsz, Mm, Nn, act);
    // 10) masked PGD iter 1
    lam_init_mask_split<<<(int)(((size_t)Bsz * Mm) / EW), EW>>>(msk, act, lAhi, lAlo, Bsz * Mm);

    // 11) masked PGD iters 2..10 on tensor cores
    curh = lAhi; curl = lAlo; nxth = lBhi; nxtl = lBlo;
    for (int it = 1; it < 10; it++) {
        int last = (it == 9);
        pgd_mma<<<gT, blk, DSMEM>>>(curh, curl, Qhi, Qlo, msk, act,
                                    nxth, nxtl, lamf, last, 1);
        __nv_bfloat16* t;
        t = curh; curh = nxth; nxth = t;
        t = curl; curl = nxtl; nxtl = t;
    }

    // 12) out = u - lam @ A
    sgemm<false, EPI_RES><<<gBn, blk>>>(lamf, A, out, Bsz, Nn, Mm, u);
}

// round 5
// speedup vs baseline: 4.0348x; 1.2208x over previous
#include <cuda_runtime.h>
#include <cuda_bf16.h>
#include <cstddef>
#include <cstdint>

// Problem constants (B=4096, n=512, m=1024)
#define Bsz 4096
#define Nn  512
#define Mm  1024
#define STEPC 0.01f
#define TOLV 1e-5f

// ---- tensor-core PGD tile config ----
#define TM 128
#define TN 256
#define KC 64
#define NCH (Mm / KC)          // 16 K-chunks
#define TILEA_B 16384          // 128x64 bf16 tile bytes
#define TILEB_B 32768          // 256x64 bf16 tile bytes
#define OFF_ALO 16384
#define OFF_BHI 32768
#define OFF_BLO 65536
#define STG_SZ  98304          // 96 KB per stage
#define DSMEM   (2 * STG_SZ + 1024)

// tcgen05 is arch-specific: only present in the sm_103a device pass.
#if defined(__CUDA_ARCH__) && defined(__CUDA_ARCH_FEAT_SM103_ALL)
#define HAS_TCGEN05 1
#else
#define HAS_TCGEN05 0
#endif

// ---------------- device scratch (allocation-free) ----------------
__device__ __align__(128) float g_Q[Mm * Mm];
__device__ __align__(128) float g_xu[Bsz * Nn];
__device__ __align__(128) float g_c[(size_t)Bsz * Mm];
__device__ __align__(128) float g_msk[(size_t)Bsz * Mm];
__device__ __align__(128) float g_act[(size_t)Bsz * Mm];
__device__ __align__(128) float g_z[Bsz * Nn];
__device__ __align__(128) float g_lamf[(size_t)Bsz * Mm];
// tiled + pre-swizzled operand images (SW128 SMEM image, contiguous per tile)
__device__ __align__(128) __nv_bfloat16 g_Qhi[Mm * Mm];          // [4 nb][16 ch][256x64]
__device__ __align__(128) __nv_bfloat16 g_Qlo[Mm * Mm];
__device__ __align__(128) __nv_bfloat16 g_lAhi[(size_t)Bsz * Mm]; // [32 bm][16 ch][128x64]
__device__ __align__(128) __nv_bfloat16 g_lAlo[(size_t)Bsz * Mm];
__device__ __align__(128) __nv_bfloat16 g_lBhi[(size_t)Bsz * Mm];
__device__ __align__(128) __nv_bfloat16 g_lBlo[(size_t)Bsz * Mm];

// ---------------- PTX helpers (generic; safe on all targets) ----------------
__device__ __forceinline__ uint32_t s2u(const void* p) {
    uint32_t a;
    asm("{ .reg .u64 t; cvta.to.shared.u64 t, %1; cvt.u32.u64 %0, t; }"
        : "=r"(a) : "l"(p));
    return a;
}

__device__ __forceinline__ uint32_t swz(uint32_t off) {
    return off ^ ((off >> 3) & 0x70);
}

__device__ __forceinline__ void mbar_init(uint32_t a, uint32_t cnt) {
    asm volatile("mbarrier.init.shared.b64 [%0], %1;" :: "r"(a), "r"(cnt) : "memory");
}

__device__ __forceinline__ void mbar_expect_tx(uint32_t a, uint32_t bytes) {
    asm volatile("mbarrier.arrive.expect_tx.shared.b64 _, [%0], %1;"
                 :: "r"(a), "r"(bytes) : "memory");
}

__device__ __forceinline__ void mbar_wait(uint32_t a, uint32_t phase) {
    uint32_t done = 0;
    while (!done) {
        asm volatile(
            "{ .reg .pred p; mbarrier.try_wait.parity.shared.b64 p, [%1], %2; "
            "selp.b32 %0, 1, 0, p; }"
            : "=r"(done) : "r"(a), "r"(phase) : "memory");
    }
}

// bulk async copy: contiguous GMEM -> SMEM, completion via mbarrier tx bytes
__device__ __forceinline__ void bulk_g2s(uint32_t dst, const void* src,
                                         uint32_t bytes, uint32_t mbar) {
    asm volatile(
        "cp.async.bulk.shared::cluster.global.mbarrier::complete_tx::bytes "
        "[%0], [%1], %2, [%3];"
        :: "r"(dst), "l"(src), "r"(bytes), "r"(mbar) : "memory");
}

// SW128 K-major SMEM descriptor (LBO=1, SBO=64, version=1, layout=SW128)
__device__ __forceinline__ uint64_t mkdesc(uint32_t addr) {
    return ((uint64_t)2 << 61) | ((uint64_t)1 << 46) | ((uint64_t)64 << 32)
         | ((uint64_t)1 << 16) | ((addr >> 4) & 0x3FFF);
}

// idesc kind::f16: dtype=F32, atype=btype=BF16, N=TN, M=128
#define PGD_IDESC ((1u<<4) | (1u<<7) | (1u<<10) | ((TN/8)<<17) | ((128/16)<<24))

__device__ __forceinline__ float bfbits2f(uint16_t u) {
    __nv_bfloat16_raw r; r.x = u;
    return __bfloat162float(__nv_bfloat16(r));
}
__device__ __forceinline__ uint16_t f2bfbits(float f) {
    __nv_bfloat16 h = __float2bfloat16(f);
    __nv_bfloat16_raw r = (__nv_bfloat16_raw)h;
    return r.x;
}

#if HAS_TCGEN05
// ---------------- tcgen05 helpers (sm_103a pass only) ----------------
__device__ __forceinline__ void mma_f16_ss(uint32_t d, uint64_t a, uint64_t b,
                                           uint32_t idesc, uint32_t en) {
    asm volatile(
        "{\n\t.reg .pred p;\n\tsetp.ne.u32 p, %5, 0;\n\t"
        "tcgen05.mma.cta_group::1.kind::f16 [%0], %1, %2, %3, {%4,%4,%4,%4}, p;\n\t}"
        :: "r"(d), "l"(a), "l"(b), "r"(idesc), "r"(0u), "r"(en) : "memory");
}

__device__ __forceinline__ void tc_commit(uint32_t mbar) {
    asm volatile(
        "tcgen05.commit.cta_group::1.mbarrier::arrive::one.shared::cluster.b64 [%0];"
        :: "r"(mbar) : "memory");
}

#define TC_ALLOC(sres, n) \
    asm volatile("tcgen05.alloc.cta_group::1.sync.aligned.shared::cta.b32 [%0], %1;" \
                 :: "r"(sres), "r"((uint32_t)(n)) : "memory")
#define TC_RELINQ() \
    asm volatile("tcgen05.relinquish_alloc_permit.cta_group::1.sync.aligned;")
#define TC_DEALLOC(t, n) \
    asm volatile("tcgen05.dealloc.cta_group::1.sync.aligned.b32 %0, %1;" :: "r"(t), "r"((uint32_t)(n)))
#define TC_FENCE_AFTER()  asm volatile("tcgen05.fence::after_thread_sync;" ::: "memory")
#define TC_WAIT_LD()      asm volatile("tcgen05.wait::ld.sync.aligned;" ::: "memory")

#define LDTM_X32(r, a) \
    asm volatile( \
        "tcgen05.ld.sync.aligned.32x32b.x32.b32 " \
        "{%0,%1,%2,%3,%4,%5,%6,%7,%8,%9,%10,%11,%12,%13,%14,%15," \
        "%16,%17,%18,%19,%20,%21,%22,%23,%24,%25,%26,%27,%28,%29,%30,%31}, [%32];" \
        : "=r"((r)[0]),"=r"((r)[1]),"=r"((r)[2]),"=r"((r)[3]), \
          "=r"((r)[4]),"=r"((r)[5]),"=r"((r)[6]),"=r"((r)[7]), \
          "=r"((r)[8]),"=r"((r)[9]),"=r"((r)[10]),"=r"((r)[11]), \
          "=r"((r)[12]),"=r"((r)[13]),"=r"((r)[14]),"=r"((r)[15]), \
          "=r"((r)[16]),"=r"((r)[17]),"=r"((r)[18]),"=r"((r)[19]), \
          "=r"((r)[20]),"=r"((r)[21]),"=r"((r)[22]),"=r"((r)[23]), \
          "=r"((r)[24]),"=r"((r)[25]),"=r"((r)[26]),"=r"((r)[27]), \
          "=r"((r)[28]),"=r"((r)[29]),"=r"((r)[30]),"=r"((r)[31]) \
        : "r"(a))
#endif  // HAS_TCGEN05

// ---------------------------------------------------------------------------
// Tensor-core PGD iteration, bulk-copy pipelined.
//   Operands live in GMEM as pre-swizzled SW128 tile images:
//     A (lam hi/lo): tile (bm, ch) = 16 KB at ((bm*16+ch)*16384)
//     B (Q hi/lo):   tile (nb, ch) = 32 KB at ((nb*16+ch)*32768)
//   acc = Ahi@Bhi + Ahi@Blo + Alo@Bhi  (fp32 TMEM)
//   v = relu(lam_old - step*(acc - c)) [*act] ; write tiled hi/lo (+fp32)
// ---------------------------------------------------------------------------
__global__ void __launch_bounds__(256, 1) pgd_mma(
    const __nv_bfloat16* __restrict__ Ahi, const __nv_bfloat16* __restrict__ Alo,
    const __nv_bfloat16* __restrict__ Bhi, const __nv_bfloat16* __restrict__ Blo,
    const float* __restrict__ cc, const float* __restrict__ act,
    __nv_bfloat16* __restrict__ Ohi, __nv_bfloat16* __restrict__ Olo,
    float* __restrict__ Of32, int writeF32, int masked)
{
#if HAS_TCGEN05
    extern __shared__ char draw[];
    const uint32_t dsm = (s2u(draw) + 1023u) & ~1023u;

    __shared__ uint32_t s_tmem;
    __shared__ __align__(8) uint64_t s_bar[5];   // full0, full1, empty0, empty1, done

    const int tid  = threadIdx.x;
    const int wid  = tid >> 5;
    const int lane = tid & 31;
    const int bm0  = blockIdx.y * TM;
    const int bn0  = blockIdx.x * TN;

    const uint32_t f0 = s2u(&s_bar[0]);
    const uint32_t f1 = s2u(&s_bar[1]);
    const uint32_t e0 = s2u(&s_bar[2]);
    const uint32_t e1 = s2u(&s_bar[3]);
    const uint32_t db = s2u(&s_bar[4]);

    if (wid == 0) TC_ALLOC(s2u(&s_tmem), 256);
    if (tid == 0) {
        mbar_init(f0, 1); mbar_init(f1, 1);
        mbar_init(e0, 1); mbar_init(e1, 1);
        mbar_init(db, 1);
    }
    __syncthreads();
    uint32_t tmem;
    asm volatile("ld.shared.b32 %0, [%1];" : "=r"(tmem) : "r"(s2u(&s_tmem)));

    // ---------- single-thread pipelined mainloop ----------
    if (tid == 0) {
        const char* aH = (const char*)Ahi + (size_t)blockIdx.y * 16 * TILEA_B;
        const char* aL = (const char*)Alo + (size_t)blockIdx.y * 16 * TILEA_B;
        const char* bH = (const char*)Bhi + (size_t)blockIdx.x * 16 * TILEB_B;
        const char* bL = (const char*)Blo + (size_t)blockIdx.x * 16 * TILEB_B;

        auto loadch = [&](int ch) {
            const int s = ch & 1;
            const uint32_t fb = s ? f1 : f0;
            const uint32_t st = dsm + (uint32_t)s * STG_SZ;
            mbar_expect_tx(fb, (uint32_t)STG_SZ);
            bulk_g2s(st,           aH + (size_t)ch * TILEA_B, TILEA_B, fb);
            bulk_g2s(st + OFF_ALO, aL + (size_t)ch * TILEA_B, TILEA_B, fb);
            bulk_g2s(st + OFF_BHI, bH + (size_t)ch * TILEB_B, TILEB_B, fb);
            bulk_g2s(st + OFF_BLO, bL + (size_t)ch * TILEB_B, TILEB_B, fb);
        };

        loadch(0);
        loadch(1);

        uint32_t phf[2] = {0, 0}, phe[2] = {0, 0};
#pragma unroll 1
        for (int ch = 0; ch < NCH; ch++) {
            const int s = ch & 1;
            mbar_wait(s ? f1 : f0, phf[s]); phf[s] ^= 1;

            const uint32_t st = dsm + (uint32_t)s * STG_SZ;
            const uint64_t dah = mkdesc(st);
            const uint64_t dal = mkdesc(st + OFF_ALO);
            const uint64_t dbh = mkdesc(st + OFF_BHI);
            const uint64_t dbl = mkdesc(st + OFF_BLO);
#pragma unroll
            for (int ks = 0; ks < 4; ks++) {
                mma_f16_ss(tmem, dah + ks * 2, dbh + ks * 2, PGD_IDESC,
                           (ch == 0 && ks == 0) ? 0u : 1u);
                mma_f16_ss(tmem, dah + ks * 2, dbl + ks * 2, PGD_IDESC, 1u);
                mma_f16_ss(tmem, dal + ks * 2, dbh + ks * 2, PGD_IDESC, 1u);
            }
            tc_commit(s ? e1 : e0);

            if (ch + 2 < NCH) {
                mbar_wait(s ? e1 : e0, phe[s]); phe[s] ^= 1;
                loadch(ch + 2);
            }
        }
        tc_commit(db);
    }

    mbar_wait(db, 0);
    TC_FENCE_AFTER();

    // ---------- fused epilogue (tiled lam, linear c/act/f32) ----------
    const int sp   = wid & 3;
    const int half = wid >> 2;
    const int lr   = sp * 32 + lane;       // local row 0..127
    const int r    = bm0 + lr;

#pragma unroll 1
    for (int cb = 0; cb < 128; cb += 32) {
        uint32_t dreg[32];
        LDTM_X32(dreg, tmem + half * 128 + cb);
        TC_WAIT_LD();

        const int coff  = half * 128 + cb;            // 0..224, 32-col span
        const int chunk = coff >> 6;                   // within this CTA's 4 chunks? no:
        // global chunk index for tiled lam addressing
        const int gch   = (bn0 >> 6) + chunk;
        const int lc0   = coff & 63;
        const size_t tb = ((size_t)(blockIdx.y * 16 + gch)) * TILEA_B;
        const size_t blin = (size_t)r * Mm + bn0 + coff;

#pragma unroll
        for (int j0 = 0; j0 < 32; j0 += 4) {
            const uint32_t boff = swz((uint32_t)(lr * 128 + (lc0 + j0) * 2));
            float4 cv = *(const float4*)&cc[blin + j0];
            uint64_t h4 = *(const uint64_t*)((const char*)Ahi + tb + boff);
            uint64_t l4 = *(const uint64_t*)((const char*)Alo + tb + boff);
            float4 av;
            if (masked) av = *(const float4*)&act[blin + j0];
            const float* cvp = (const float*)&cv;
            const float* avp = (const float*)&av;
            uint16_t oh[4], ol[4];
            float of[4];
#pragma unroll
            for (int k = 0; k < 4; k++) {
                float lamold = bfbits2f((uint16_t)(h4 >> (16 * k)))
                             + bfbits2f((uint16_t)(l4 >> (16 * k)));
                float acc = __uint_as_float(dreg[j0 + k]);
                float v = fmaxf(lamold - STEPC * (acc - cvp[k]), 0.f);
                if (masked) v *= avp[k];
                uint16_t hb = f2bfbits(v);
                oh[k] = hb;
                ol[k] = f2bfbits(v - bfbits2f(hb));
                of[k] = v;
            }
            uint64_t ohp = (uint64_t)oh[0] | ((uint64_t)oh[1] << 16)
                         | ((uint64_t)oh[2] << 32) | ((uint64_t)oh[3] << 48);
            uint64_t olp = (uint64_t)ol[0] | ((uint64_t)ol[1] << 16)
                         | ((uint64_t)ol[2] << 32) | ((uint64_t)ol[3] << 48);
            *(uint64_t*)((char*)Ohi + tb + boff) = ohp;
            *(uint64_t*)((char*)Olo + tb + boff) = olp;
            if (writeF32) *(float4*)&Of32[blin + j0] = make_float4(of[0], of[1], of[2], of[3]);
        }
    }

    __syncthreads();
    if (wid == 0) { TC_RELINQ(); TC_DEALLOC(tmem, 256); }
#endif  // HAS_TCGEN05
}

// ---------------------------------------------------------------------------
// fp32 SIMT SGEMM (peripheral GEMMs)
// ---------------------------------------------------------------------------
enum { EPI_NONE = 0, EPI_SUB_B, EPI_RES, EPI_ACTIVE, EPI_MASKED };

template <bool TB, int EPI>
__global__ void __launch_bounds__(256, 2) sgemm(
    const float* __restrict__ Ag, const float* __restrict__ Bg,
    float* __restrict__ Cg, int M, int N, int K,
    const float* __restrict__ e1)
{
    constexpr int BM = 128, BN = 128, BK = 16;
    __shared__ float As[BK][BM];
    __shared__ float Bs[BK][BN];

    const int tid  = threadIdx.x;
    const int bm0  = blockIdx.y * BM;
    const int bn0  = blockIdx.x * BN;
    const int cRow = (tid >> 4) * 8;
    const int cCol = (tid & 15) * 8;

    float acc[8][8];
#pragma unroll
    for (int i = 0; i < 8; i++)
#pragma unroll
        for (int j = 0; j < 8; j++) acc[i][j] = 0.f;

    for (int k0 = 0; k0 < K; k0 += BK) {
#pragma unroll
        for (int l = 0; l < 2; l++) {
            int f = tid + l * 256, row = f >> 2, c4 = f & 3;
            float4 v = *(const float4*)&Ag[(size_t)(bm0 + row) * K + k0 + c4 * 4];
            As[c4 * 4 + 0][row] = v.x; As[c4 * 4 + 1][row] = v.y;
            As[c4 * 4 + 2][row] = v.z; As[c4 * 4 + 3][row] = v.w;
        }
        if (TB) {
#pragma unroll
            for (int l = 0; l < 2; l++) {
                int f = tid + l * 256, row = f >> 2, c4 = f & 3;
                float4 v = *(const float4*)&Bg[(size_t)(bn0 + row) * K + k0 + c4 * 4];
                Bs[c4 * 4 + 0][row] = v.x; Bs[c4 * 4 + 1][row] = v.y;
                Bs[c4 * 4 + 2][row] = v.z; Bs[c4 * 4 + 3][row] = v.w;
            }
        } else {
#pragma unroll
            for (int l = 0; l < 2; l++) {
                int f = tid + l * 256, row = f >> 5, c4 = f & 31;
                float4 v = *(const float4*)&Bg[(size_t)(k0 + row) * N + bn0 + c4 * 4];
                *(float4*)&Bs[row][c4 * 4] = v;
            }
        }
        __syncthreads();
#pragma unroll
        for (int k = 0; k < BK; k++) {
            float4 a0 = *(const float4*)&As[k][cRow];
            float4 a1 = *(const float4*)&As[k][cRow + 4];
            float4 b0 = *(const float4*)&Bs[k][cCol];
            float4 b1 = *(const float4*)&Bs[k][cCol + 4];
            float a[8] = {a0.x, a0.y, a0.z, a0.w, a1.x, a1.y, a1.z, a1.w};
            float b[8] = {b0.x, b0.y, b0.z, b0.w, b1.x, b1.y, b1.z, b1.w};
#pragma unroll
            for (int i = 0; i < 8; i++)
#pragma unroll
                for (int j = 0; j < 8; j++) acc[i][j] += a[i] * b[j];
        }
        __syncthreads();
    }

#pragma unroll
    for (int i = 0; i < 8; i++) {
        const int r = bm0 + cRow + i;
#pragma unroll
        for (int j = 0; j < 8; j++) {
            const int cl = bn0 + cCol + j;
            const size_t idx = (size_t)r * N + cl;
            const float v = acc[i][j];
            if (EPI == EPI_NONE)        Cg[idx] = v;
            else if (EPI == EPI_SUB_B)  Cg[idx] = v - e1[cl];
            else if (EPI == EPI_RES)    Cg[idx] = e1[idx] - v;
            else if (EPI == EPI_ACTIVE) Cg[idx] = (v >= e1[cl] - TOLV) ? 1.f : 0.f;
            else if (EPI == EPI_MASKED) Cg[idx] = v * e1[idx];
        }
    }
}

// ---------------- small elementwise kernels ----------------
__global__ void add_kernel(const float* __restrict__ x, const float* __restrict__ u,
                           float* __restrict__ o, int n)
{
    int i = blockIdx.x * blockDim.x + threadIdx.x;
    if (i < n) o[i] = x[i] + u[i];
}

// split Q fp32 -> tiled/swizzled bf16 hi/lo B-image: tile (nb=row/256, ch=col/64)
__global__ void split_q_tiled(const float* __restrict__ s,
                              __nv_bfloat16* __restrict__ hi,
                              __nv_bfloat16* __restrict__ lo)
{
    int i = blockIdx.x * blockDim.x + threadIdx.x;
    if (i >= Mm * Mm) return;
    int qr = i >> 10, qc = i & 1023;
    int nb = qr >> 8, lrow = qr & 255, ch = qc >> 6, lc = qc & 63;
    size_t tb = ((size_t)(nb * 16 + ch)) * TILEB_B;
    uint32_t boff = swz((uint32_t)(lrow * 128 + lc * 2));
    float v = s[i];
    __nv_bfloat16 h = __float2bfloat16(v);
    *(__nv_bfloat16*)((char*)hi + tb + boff) = h;
    *(__nv_bfloat16*)((char*)lo + tb + boff) = __float2bfloat16(v - __bfloat162float(h));
}

// lam init -> tiled/swizzled A-image: tile (bm=row/128, ch=col/64)
__global__ void lam_init_tiled(const float* __restrict__ c,
                               __nv_bfloat16* __restrict__ hi,
                               __nv_bfloat16* __restrict__ lo)
{
    int i = blockIdx.x * blockDim.x + threadIdx.x;
    if (i >= Bsz * Mm) return;
    int r = i >> 10, cx = i & 1023;
    int bm = r >> 7, lrow = r & 127, ch = cx >> 6, lc = cx & 63;
    size_t tb = ((size_t)(bm * 16 + ch)) * TILEA_B;
    uint32_t boff = swz((uint32_t)(lrow * 128 + lc * 2));
    float v = fmaxf(STEPC * c[i], 0.f);
    __nv_bfloat16 h = __float2bfloat16(v);
    *(__nv_bfloat16*)((char*)hi + tb + boff) = h;
    *(__nv_bfloat16*)((char*)lo + tb + boff) = __float2bfloat16(v - __bfloat162float(h));
}

__global__ void lam_init_mask_tiled(const float* __restrict__ m, const float* __restrict__ a,
                                    __nv_bfloat16* __restrict__ hi,
                                    __nv_bfloat16* __restrict__ lo)
{
    int i = blockIdx.x * blockDim.x + threadIdx.x;
    if (i >= Bsz * Mm) return;
    int r = i >> 10, cx = i & 1023;
    int bm = r >> 7, lrow = r & 127, ch = cx >> 6, lc = cx & 63;
    size_t tb = ((size_t)(bm * 16 + ch)) * TILEA_B;
    uint32_t boff = swz((uint32_t)(lrow * 128 + lc * 2));
    float v = fmaxf(STEPC * m[i], 0.f) * a[i];
    __nv_bfloat16 h = __float2bfloat16(v);
    *(__nv_bfloat16*)((char*)hi + tb + boff) = h;
    *(__nv_bfloat16*)((char*)lo + tb + boff) = __float2bfloat16(v - __bfloat162float(h));
}

// ---------------------------------------------------------------------------
extern "C" void kernel_launch(void* const* d_in, const int* in_sizes, int n_in,
                              void* d_out, int out_size)
{
    const float* x = (const float*)d_in[0];
    const float* u = (const float*)d_in[1];
    const float* A = (const float*)d_in[2];   // [m, n]
    const float* b = (const float*)d_in[3];   // [m]
    float* out = (float*)d_out;

    float *Q, *xu, *c, *msk, *act, *z, *lamf;
    __nv_bfloat16 *Qhi, *Qlo, *lAhi, *lAlo, *lBhi, *lBlo;
    cudaGetSymbolAddress((void**)&Q,    g_Q);
    cudaGetSymbolAddress((void**)&xu,   g_xu);
    cudaGetSymbolAddress((void**)&c,    g_c);
    cudaGetSymbolAddress((void**)&msk,  g_msk);
    cudaGetSymbolAddress((void**)&act,  g_act);
    cudaGetSymbolAddress((void**)&z,    g_z);
    cudaGetSymbolAddress((void**)&lamf, g_lamf);
    cudaGetSymbolAddress((void**)&Qhi,  g_Qhi);
    cudaGetSymbolAddress((void**)&Qlo,  g_Qlo);
    cudaGetSymbolAddress((void**)&lAhi, g_lAhi);
    cudaGetSymbolAddress((void**)&lAlo, g_lAlo);
    cudaGetSymbolAddress((void**)&lBhi, g_lBhi);
    cudaGetSymbolAddress((void**)&lBlo, g_lBlo);

    cudaFuncSetAttribute(pgd_mma, cudaFuncAttributeMaxDynamicSharedMemorySize, DSMEM);

    const dim3 blk(256);
    const dim3 gQ(Mm / 128, Mm / 128);
    const dim3 gBm(Mm / 128, Bsz / 128);
    const dim3 gBn(Nn / 128, Bsz / 128);
    const dim3 gT(Mm / TN, Bsz / TM);        // 4 x 32 = 128 CTAs
    const int EW = 256;

    // 1) Q = A @ A^T  (fp32)
    sgemm<true, EPI_NONE><<<gQ, blk>>>(A, A, Q, Mm, Mm, Nn, nullptr);
    // 2) split Q -> tiled/swizzled bf16 hi/lo
    split_q_tiled<<<(Mm * Mm) / EW, EW>>>(Q, Qhi, Qlo);
    // 3) xu = x + u
    add_kernel<<<(Bsz * Nn) / EW, EW>>>(x, u, xu, Bsz * Nn);
    // 4) c = xu @ A^T - b
    sgemm<true, EPI_SUB_B><<<gBm, blk>>>(xu, A, c, Bsz, Mm, Nn, b);
    // 5) PGD iter 1: lam = relu(step*c), tiled split
    lam_init_tiled<<<(int)(((size_t)Bsz * Mm) / EW), EW>>>(c, lAhi, lAlo);

    // 6) PGD iters 2..50 on tensor cores
    __nv_bfloat16 *curh = lAhi, *curl = lAlo, *nxth = lBhi, *nxtl = lBlo;
    for (int it = 1; it < 50; it++) {
        int last = (it == 49);
        pgd_mma<<<gT, blk, DSMEM>>>(curh, curl, Qhi, Qlo, c, nullptr,
                                    nxth, nxtl, lamf, last, 0);
        __nv_bfloat16* t;
        t = curh; curh = nxth; nxth = t;
        t = curl; curl = nxtl; nxtl = t;
    }

    // 7) z = xu - lam @ A
    sgemm<false, EPI_RES><<<gBn, blk>>>(lamf, A, z, Bsz, Nn, Mm, xu);
    // 8) active = (z @ A^T >= b - TOL)
    sgemm<true, EPI_ACTIVE><<<gBm, blk>>>(z, A, act, Bsz, Mm, Nn, b);
    // 9) masked = (u @ A^T) * active
    sgemm<true, EPI_MASKED><<<gBm, blk>>>(u, A, msk, Bsz, Mm, Nn, act);
    // 10) masked PGD iter 1
    lam_init_mask_tiled<<<(int)(((size_t)Bsz * Mm) / EW), EW>>>(msk, act, lAhi, lAlo);

    // 11) masked PGD iters 2..10 on tensor cores
    curh = lAhi; curl = lAlo; nxth = lBhi; nxtl = lBlo;
    for (int it = 1; it < 10; it++) {
        int last = (it == 9);
        pgd_mma<<<gT, blk, DSMEM>>>(curh, curl, Qhi, Qlo, msk, act,
                                    nxth, nxtl, lamf, last, 1);
        __nv_bfloat16* t;
        t = curh; curh = nxth; nxth = t;
        t = curl; curl = nxtl; nxtl = t;
    }

    // 12) out = u - lam @ A
    sgemm<false, EPI_RES><<<gBn, blk>>>(lamf, A, out, Bsz, Nn, Mm, u);
}